// round 17
// baseline (speedup 1.0000x reference)
#include <cuda_runtime.h>
#include <cuda_bf16.h>

// Shapes: B=4, H=12, N=4096, D=64, E=32
#define BB      4
#define HH      12
#define NN      4096
#define DD      64
#define EE      32
#define TWOE    64
#define THREADS 64     // threads per block
#define TOKENS  128    // tokens per block (2 per thread)

// Output layout (concatenated flattened tuple, fp32):
#define SZ_HDE  (24576ll)
#define OFF_ES  (12582912ll)
#define OFF_RS  (18874368ll)
#define OFF_WE0 (25165824ll)
#define OFF_WR0 (25190400ll)
#define OFF_Q   (25214976ll)
#define OFF_K   (37797888ll)
#define OFF_LAM (50380800ll)

typedef unsigned long long u64;

__device__ __forceinline__ u64 pack2(float lo, float hi) {
    u64 r;
    asm("mov.b64 %0, {%1, %2};" : "=l"(r) : "f"(lo), "f"(hi));
    return r;
}
__device__ __forceinline__ void unpack2(u64 v, float& lo, float& hi) {
    asm("mov.b64 {%0, %1}, %2;" : "=f"(lo), "=f"(hi) : "l"(v));
}
// Packed dual-fp32 FMA (sm_100+): exact IEEE fp32 on both lanes.
__device__ __forceinline__ u64 fma2(u64 a, u64 b, u64 c) {
    u64 d;
    asm("fma.rn.f32x2 %0, %1, %2, %3;" : "=l"(d) : "l"(a), "l"(b), "l"(c));
    return d;
}

__device__ __forceinline__ void load_row(float* v, const float* g) {
    const float4* s = (const float4*)g;
    #pragma unroll
    for (int i = 0; i < DD / 4; ++i) {
        float4 t = s[i];
        v[4*i] = t.x; v[4*i+1] = t.y; v[4*i+2] = t.z; v[4*i+3] = t.w;
    }
}
__device__ __forceinline__ void store_row(float* g, const float* v) {
    float4* d = (float4*)g;
    #pragma unroll
    for (int i = 0; i < DD / 4; ++i)
        d[i] = make_float4(v[4*i], v[4*i+1], v[4*i+2], v[4*i+3]);
}
// Normalize in place: exact same arithmetic as the verified kernel.
__device__ __forceinline__ void l2norm(float* v) {
    float ss = 0.f;
    #pragma unroll
    for (int i = 0; i < DD; ++i) ss = fmaf(v[i], v[i], ss);
    float inv = rsqrtf(fmaxf(ss, 1e-24f));   // ss=||x||^2; matches max(||x||,1e-12)
    #pragma unroll
    for (int i = 0; i < DD; ++i) v[i] *= inv;
}

__global__ __launch_bounds__(THREADS, 4) void pca_fused_kernel(
    const float* __restrict__ Q, const float* __restrict__ K,
    const float* __restrict__ we, const float* __restrict__ wr,
    const float* __restrict__ mask, const float* __restrict__ W,
    const float* __restrict__ bias, float* __restrict__ out)
{
    __shared__ __align__(16) float s_we[DD * EE];   // 8 KB
    __shared__ __align__(16) float s_wr[DD * EE];   // 8 KB
    __shared__ __align__(16) float s_Wt[TWOE * DD]; // 16 KB  Wt[j][d] = W[d][j]
    __shared__ __align__(16) float s_b[DD];

    const int tileIdx = blockIdx.x;   // 0..31
    const int h       = blockIdx.y;   // 0..11
    const int b       = blockIdx.z;   // 0..3
    const int tid     = threadIdx.x;  // 0..63

    // ---- stage weights ----
    {
        const float* we_h = we + (long long)h * DD * EE;
        const float* wr_h = wr + (long long)h * DD * EE;
        #pragma unroll
        for (int i = tid; i < DD * EE; i += THREADS) {
            s_we[i] = we_h[i];
            s_wr[i] = wr_h[i];
        }
        #pragma unroll
        for (int i = tid; i < TWOE * DD; i += THREADS) {
            int j = i >> 6;        // column of W (0..63)
            int d = i & 63;        // row of W    (0..63)
            s_Wt[i] = W[d * TWOE + j];
        }
        s_b[tid] = bias[tid];      // THREADS == DD == 64
    }
    __syncthreads();

    const int base = tileIdx * TOKENS;
    const long long bh    = (long long)(b * HH + h);
    const long long nrow0 = bh * NN + base + tid;        // token 0
    const long long nrow1 = bh * NN + base + tid + 64;   // token 1
    const long long off0  = nrow0 * DD, off1 = nrow1 * DD;
    const long long eo0   = nrow0 * EE, eo1 = nrow1 * EE;

    float* out_attn = out;
    float* out_es   = out + OFF_ES;
    float* out_rs   = out + OFF_RS;
    float* out_q    = out + OFF_Q;
    float* out_k    = out + OFF_K;

    u64 ea[EE / 2], eb[EE / 2];   // escore pairs, tokens 0/1
    u64 ra[EE / 2], rb[EE / 2];   // rscore pairs

    // ================= Q phase: both tokens =================
    {
        float q0[DD], q1[DD];
        load_row(q0, Q + off0);
        load_row(q1, Q + off1);
        l2norm(q0);
        l2norm(q1);
        store_row(out_q + off0, q0);
        store_row(out_q + off1, q1);

        #pragma unroll
        for (int j = 0; j < EE / 2; ++j) { ea[j] = 0ull; eb[j] = 0ull; }
        #pragma unroll 4
        for (int d = 0; d < DD; ++d) {
            u64 qa = pack2(q0[d], q0[d]);
            u64 qb = pack2(q1[d], q1[d]);
            const ulonglong2* row = (const ulonglong2*)(s_we + d * EE);  // 8 LDS.128
            #pragma unroll
            for (int j = 0; j < 8; ++j) {
                ulonglong2 w = row[j];
                ea[2*j]   = fma2(qa, w.x, ea[2*j]);
                ea[2*j+1] = fma2(qa, w.y, ea[2*j+1]);
                eb[2*j]   = fma2(qb, w.x, eb[2*j]);
                eb[2*j+1] = fma2(qb, w.y, eb[2*j+1]);
            }
        }
        float4* d0 = (float4*)(out_es + eo0);
        float4* d1 = (float4*)(out_es + eo1);
        #pragma unroll
        for (int i = 0; i < EE / 4; ++i) {
            float a0,a1,a2,a3, b0,b1,b2,b3;
            unpack2(ea[2*i],   a0, a1); unpack2(ea[2*i+1], a2, a3);
            unpack2(eb[2*i],   b0, b1); unpack2(eb[2*i+1], b2, b3);
            d0[i] = make_float4(a0, a1, a2, a3);
            d1[i] = make_float4(b0, b1, b2, b3);
        }
    }

    // ================= K phase: both tokens =================
    {
        float k0[DD], k1[DD];
        load_row(k0, K + off0);
        load_row(k1, K + off1);
        l2norm(k0);
        l2norm(k1);
        store_row(out_k + off0, k0);
        store_row(out_k + off1, k1);

        #pragma unroll
        for (int j = 0; j < EE / 2; ++j) { ra[j] = 0ull; rb[j] = 0ull; }
        #pragma unroll 4
        for (int d = 0; d < DD; ++d) {
            u64 ka = pack2(k0[d], k0[d]);
            u64 kb = pack2(k1[d], k1[d]);
            const ulonglong2* row = (const ulonglong2*)(s_wr + d * EE);
            #pragma unroll
            for (int j = 0; j < 8; ++j) {
                ulonglong2 w = row[j];
                ra[2*j]   = fma2(ka, w.x, ra[2*j]);
                ra[2*j+1] = fma2(ka, w.y, ra[2*j+1]);
                rb[2*j]   = fma2(kb, w.x, rb[2*j]);
                rb[2*j+1] = fma2(kb, w.y, rb[2*j+1]);
            }
        }
        float4* d0 = (float4*)(out_rs + eo0);
        float4* d1 = (float4*)(out_rs + eo1);
        #pragma unroll
        for (int i = 0; i < EE / 4; ++i) {
            float a0,a1,a2,a3, b0,b1,b2,b3;
            unpack2(ra[2*i],   a0, a1); unpack2(ra[2*i+1], a2, a3);
            unpack2(rb[2*i],   b0, b1); unpack2(rb[2*i+1], b2, b3);
            d0[i] = make_float4(a0, a1, a2, a3);
            d1[i] = make_float4(b0, b1, b2, b3);
        }
    }

    // ================= attn: both tokens share every Wt read =================
    {
        const float m0 = mask[(long long)b * NN + base + tid];
        const float m1 = mask[(long long)b * NN + base + tid + 64];
        const ulonglong2* b2v = (const ulonglong2*)s_b;
        float4* da0 = (float4*)(out_attn + off0);
        float4* da1 = (float4*)(out_attn + off1);

        #pragma unroll
        for (int half = 0; half < 2; ++half) {
            u64 accA[16], accB[16];   // 32-float half of D, per token
            #pragma unroll
            for (int j = 0; j < 8; ++j) {
                ulonglong2 bb = b2v[half * 8 + j];
                accA[2*j] = bb.x; accA[2*j+1] = bb.y;
                accB[2*j] = bb.x; accB[2*j+1] = bb.y;
            }

            #pragma unroll 4
            for (int e = 0; e < EE; ++e) {
                float s0lo, s0hi; unpack2(ea[e >> 1], s0lo, s0hi);
                float s1lo, s1hi; unpack2(eb[e >> 1], s1lo, s1hi);
                float s0 = (e & 1) ? s0hi : s0lo;
                float s1 = (e & 1) ? s1hi : s1lo;
                u64 sa = pack2(s0, s0), sb = pack2(s1, s1);
                const ulonglong2* row = (const ulonglong2*)(s_Wt + e * DD) + half * 8;
                #pragma unroll
                for (int j = 0; j < 8; ++j) {
                    ulonglong2 w = row[j];
                    accA[2*j]   = fma2(sa, w.x, accA[2*j]);
                    accA[2*j+1] = fma2(sa, w.y, accA[2*j+1]);
                    accB[2*j]   = fma2(sb, w.x, accB[2*j]);
                    accB[2*j+1] = fma2(sb, w.y, accB[2*j+1]);
                }
            }
            #pragma unroll 4
            for (int e = 0; e < EE; ++e) {
                float s0lo, s0hi; unpack2(ra[e >> 1], s0lo, s0hi);
                float s1lo, s1hi; unpack2(rb[e >> 1], s1lo, s1hi);
                float s0 = (e & 1) ? s0hi : s0lo;
                float s1 = (e & 1) ? s1hi : s1lo;
                u64 sa = pack2(s0, s0), sb = pack2(s1, s1);
                const ulonglong2* row = (const ulonglong2*)(s_Wt + (EE + e) * DD) + half * 8;
                #pragma unroll
                for (int j = 0; j < 8; ++j) {
                    ulonglong2 w = row[j];
                    accA[2*j]   = fma2(sa, w.x, accA[2*j]);
                    accA[2*j+1] = fma2(sa, w.y, accA[2*j+1]);
                    accB[2*j]   = fma2(sb, w.x, accB[2*j]);
                    accB[2*j+1] = fma2(sb, w.y, accB[2*j+1]);
                }
            }

            #pragma unroll
            for (int i = 0; i < 8; ++i) {
                float a0,a1,a2,a3, b0,b1,b2,b3;
                unpack2(accA[2*i],   a0, a1); unpack2(accA[2*i+1], a2, a3);
                unpack2(accB[2*i],   b0, b1); unpack2(accB[2*i+1], b2, b3);
                da0[half * 8 + i] = make_float4(a0*m0, a1*m0, a2*m0, a3*m0);
                da1[half * 8 + i] = make_float4(b0*m1, b1*m1, b2*m1, b3*m1);
            }
        }
    }
}

extern "C" void kernel_launch(void* const* d_in, const int* in_sizes, int n_in,
                              void* d_out, int out_size) {
    const float* Q    = (const float*)d_in[0];
    const float* K    = (const float*)d_in[1];
    const float* we   = (const float*)d_in[2];
    const float* wr   = (const float*)d_in[3];
    const float* mask = (const float*)d_in[4];
    const float* W    = (const float*)d_in[5];
    const float* bias = (const float*)d_in[6];
    const float* Lam  = (const float*)d_in[7];
    float* out = (float*)d_out;

    dim3 grid(NN / TOKENS, HH, BB);   // 32 x 12 x 4
    pca_fused_kernel<<<grid, THREADS>>>(Q, K, we, wr, mask, W, bias, out);

    // Pass-through outputs: we[0], wr[0], Lambda (device-to-device, capturable)
    cudaMemcpyAsync(out + OFF_WE0, we,  SZ_HDE * sizeof(float), cudaMemcpyDeviceToDevice);
    cudaMemcpyAsync(out + OFF_WR0, wr,  SZ_HDE * sizeof(float), cudaMemcpyDeviceToDevice);
    cudaMemcpyAsync(out + OFF_LAM, Lam, 384 * sizeof(float),    cudaMemcpyDeviceToDevice);
}